// round 16
// baseline (speedup 1.0000x reference)
#include <cuda_runtime.h>
#include <cuda_bf16.h>

// VQ-VAE quantizer, round 16: R15 with the B-fragment fix (ldmatrix WITHOUT
// .trans — row-major [code][k] smem IS mma's col-major B). HMMA bf16 hi/lo
// split screen + margin + exact fp32 rescue/outputs.
//   h: (256,512,32) f32 -> 131072 tokens x 32;  embeddings: (1024,32) f32
//   out f32: qst (131072*32) | indices (131072) | loss (131072)

typedef unsigned long long u64;
typedef unsigned int u32;

#define DIM     32
#define NCODES  1024
#define NTOK    131072
#define TPB     256
#define TOKPC   128                  // tokens per CTA
#define NBLK    (NTOK / TOKPC)       // 1024
#define CN      256                  // codes per smem chunk
#define NCHUNK  (NCODES / CN)        // 4
#define MARGIN  4e-5f
#define LDAB    104                  // padded row stride in bf16 (208 B)

// smem byte offsets
#define A_O    0                            // bf16 A[128][104]
#define B_O    (A_O + TOKPC * LDAB * 2)     // 26624: bf16 B[256][104]
#define H_O    (B_O + CN * LDAB * 2)        // 79872: f32 h[128][32]
#define BN_O   (H_O + TOKPC * DIM * 4)      // 96256: f32 bn[1024]
#define SA_O   (BN_O + NCODES * 4)          // 100352: f32 a[128]
#define SMEMSZ (SA_O + TOKPC * 4)           // 100864

__device__ __forceinline__ u32 smem_u32(const void* p) {
    u32 a;
    asm("{ .reg .u64 t; cvta.to.shared.u64 t, %1; cvt.u32.u64 %0, t; }"
        : "=r"(a) : "l"(p));
    return a;
}
__device__ __forceinline__ u64 pk2(float lo, float hi) {
    u64 r;
    asm("mov.b64 %0, {%1, %2};" : "=l"(r) : "f"(lo), "f"(hi));
    return r;
}
__device__ __forceinline__ void upk2(u64 v, float& lo, float& hi) {
    asm("mov.b64 {%0, %1}, %2;" : "=f"(lo), "=f"(hi) : "l"(v));
}
__device__ __forceinline__ u64 ffma2(u64 a, u64 b, u64 c) {
    u64 d;
    asm("fma.rn.f32x2 %0, %1, %2, %3;" : "=l"(d) : "l"(a), "l"(b), "l"(c));
    return d;
}
__device__ __forceinline__ u64 fadd2(u64 a, u64 b) {
    u64 d;
    asm("add.rn.f32x2 %0, %1, %2;" : "=l"(d) : "l"(a), "l"(b));
    return d;
}
__device__ __forceinline__ u64 pkkey(float k, int i) {  // key hi, idx lo
    u64 r;
    asm("mov.b64 %0, {%1, %2};" : "=l"(r) : "r"((u32)i), "r"(__float_as_uint(k)));
    return r;
}
__device__ __forceinline__ float keyof(u64 p) { return __uint_as_float((u32)(p >> 32)); }
__device__ __forceinline__ u64 umin64(u64 a, u64 b) { return a < b ? a : b; }
__device__ __forceinline__ u32 bfpack(float a, float b) {
    __nv_bfloat162 t = __floats2bfloat162_rn(a, b);
    return *reinterpret_cast<u32*>(&t);
}

__device__ __forceinline__ void ldmatrix_x4(u32& r0, u32& r1, u32& r2, u32& r3, u32 addr) {
    asm volatile("ldmatrix.sync.aligned.m8n8.x4.shared.b16 {%0,%1,%2,%3}, [%4];"
                 : "=r"(r0), "=r"(r1), "=r"(r2), "=r"(r3) : "r"(addr));
}
// B fragment: NO trans — [code][k] row-major smem is mma's col-major B.
__device__ __forceinline__ void ldmatrix_x2(u32& r0, u32& r1, u32 addr) {
    asm volatile("ldmatrix.sync.aligned.m8n8.x2.shared.b16 {%0,%1}, [%2];"
                 : "=r"(r0), "=r"(r1) : "r"(addr));
}
__device__ __forceinline__ void mma16816(float& d0, float& d1, float& d2, float& d3,
                                         u32 a0, u32 a1, u32 a2, u32 a3,
                                         u32 b0, u32 b1) {
    asm volatile(
        "mma.sync.aligned.m16n8k16.row.col.f32.bf16.bf16.f32 "
        "{%0,%1,%2,%3}, {%4,%5,%6,%7}, {%8,%9}, {%0,%1,%2,%3};"
        : "+f"(d0), "+f"(d1), "+f"(d2), "+f"(d3)
        : "r"(a0), "r"(a1), "r"(a2), "r"(a3), "r"(b0), "r"(b1));
}

// ||x||^2 and loss sum, reference-order reductions (R5-verified bit-exact).
__device__ __forceinline__ float sumsq32(const float* x) {
    float A0 = __fmul_rn(x[0], x[0]), A1 = __fmul_rn(x[1], x[1]);
    float A2 = __fmul_rn(x[2], x[2]), A3 = __fmul_rn(x[3], x[3]);
#pragma unroll
    for (int i = 1; i < 8; i++) {
        A0 = __fadd_rn(A0, __fmul_rn(x[4*i+0], x[4*i+0]));
        A1 = __fadd_rn(A1, __fmul_rn(x[4*i+1], x[4*i+1]));
        A2 = __fadd_rn(A2, __fmul_rn(x[4*i+2], x[4*i+2]));
        A3 = __fadd_rn(A3, __fmul_rn(x[4*i+3], x[4*i+3]));
    }
    return __fadd_rn(__fadd_rn(A0, A1), __fadd_rn(A2, A3));
}
__device__ __forceinline__ float sumsqdiff32(const float* q, const float* h) {
    float A0, A1, A2, A3;
    {
        float d0 = __fsub_rn(q[0], h[0]), d1 = __fsub_rn(q[1], h[1]);
        float d2 = __fsub_rn(q[2], h[2]), d3 = __fsub_rn(q[3], h[3]);
        A0 = __fmul_rn(d0, d0); A1 = __fmul_rn(d1, d1);
        A2 = __fmul_rn(d2, d2); A3 = __fmul_rn(d3, d3);
    }
#pragma unroll
    for (int i = 1; i < 8; i++) {
        float e0 = __fsub_rn(q[4*i+0], h[4*i+0]), e1 = __fsub_rn(q[4*i+1], h[4*i+1]);
        float e2 = __fsub_rn(q[4*i+2], h[4*i+2]), e3 = __fsub_rn(q[4*i+3], h[4*i+3]);
        A0 = __fadd_rn(A0, __fmul_rn(e0, e0));
        A1 = __fadd_rn(A1, __fmul_rn(e1, e1));
        A2 = __fadd_rn(A2, __fmul_rn(e2, e2));
        A3 = __fadd_rn(A3, __fmul_rn(e3, e3));
    }
    return __fadd_rn(__fadd_rn(A0, A1), __fadd_rn(A2, A3));
}

extern __shared__ char smc[];

__global__ void __launch_bounds__(TPB, 1)
vq_kernel(const float* __restrict__ H, const float* __restrict__ E,
          float* __restrict__ out) {
    const int tid = threadIdx.x, warp = tid >> 5, lane = tid & 31;
    const u32 sb = smem_u32(smc);
    __nv_bfloat16* sA = (__nv_bfloat16*)(smc + A_O);
    __nv_bfloat16* sB = (__nv_bfloat16*)(smc + B_O);
    float* sH  = (float*)(smc + H_O);
    float* sBn = (float*)(smc + BN_O);
    float* sa  = (float*)(smc + SA_O);

    // ---- build: threads 0-127 -> A rows + sH + sa; 128-255 -> code norms ----
    if (tid < TOKPC) {
        const int r = tid;
        float h[DIM];
        const float4* hp = (const float4*)(H + ((size_t)blockIdx.x * TOKPC + r) * DIM);
#pragma unroll
        for (int v = 0; v < 8; v++) {
            float4 x = hp[v];
            h[4*v+0] = x.x; h[4*v+1] = x.y; h[4*v+2] = x.z; h[4*v+3] = x.w;
        }
#pragma unroll
        for (int k = 0; k < DIM; k++) sH[r * DIM + k] = h[k];
        sa[r] = sumsq32(h);
        u32* row = (u32*)(sA + (size_t)r * LDAB);
#pragma unroll
        for (int k = 0; k < DIM; k += 2) {
            float h0 = __bfloat162float(__float2bfloat16(h[k]));
            float h1 = __bfloat162float(__float2bfloat16(h[k+1]));
            u32 hh = bfpack(h0, h1);
            u32 hl = bfpack(__fsub_rn(h[k], h0), __fsub_rn(h[k+1], h1));
            row[k/2]      = hh;     // MMA k 0-31 : h_hi
            row[16 + k/2] = hh;     // MMA k 32-63: h_hi
            row[32 + k/2] = hl;     // MMA k 64-95: h_lo
        }
    } else {
        const int base = (tid - TOKPC) * 8;
#pragma unroll 1
        for (int c = base; c < base + 8; c++) {
            float e[DIM];
            const float4* ep = (const float4*)(E + (size_t)c * DIM);
#pragma unroll
            for (int v = 0; v < 8; v++) {
                float4 x = ep[v];
                e[4*v+0] = x.x; e[4*v+1] = x.y; e[4*v+2] = x.z; e[4*v+3] = x.w;
            }
            sBn[c] = sumsq32(e);
        }
    }

    // per-thread screen state: slots 0/1 = token rows gid and gid+8
    const int gid  = lane >> 2;               // 0..7
    const int tid4 = lane & 3;                // 0..3
    const float INFP = __int_as_float(0x7f800000);
    u64 m1p[2] = {pkkey(INFP, 0), pkkey(INFP, 0)};
    float m2[2] = {INFP, INFP};

    u32 af[6][4];                              // A frags, persist all chunks
    const u64 neg2 = pk2(-2.0f, -2.0f);
    u64 aal = 0, aah = 0;

#pragma unroll 1
    for (int ch = 0; ch < NCHUNK; ch++) {
        if (ch) __syncthreads();               // drain reads before rebuild
        // build B chunk: one code row per thread, [eh, el, eh]
        {
            const int c = ch * CN + tid;
            float e[DIM];
            const float4* ep = (const float4*)(E + (size_t)c * DIM);
#pragma unroll
            for (int v = 0; v < 8; v++) {
                float4 x = ep[v];
                e[4*v+0] = x.x; e[4*v+1] = x.y; e[4*v+2] = x.z; e[4*v+3] = x.w;
            }
            u32* row = (u32*)(sB + (size_t)tid * LDAB);
#pragma unroll
            for (int k = 0; k < DIM; k += 2) {
                float e0 = __bfloat162float(__float2bfloat16(e[k]));
                float e1 = __bfloat162float(__float2bfloat16(e[k+1]));
                u32 eh = bfpack(e0, e1);
                u32 el = bfpack(__fsub_rn(e[k], e0), __fsub_rn(e[k+1], e1));
                row[k/2]      = eh;     // k 0-31 : e_hi
                row[16 + k/2] = el;     // k 32-63: e_lo
                row[32 + k/2] = eh;     // k 64-95: e_hi
            }
        }
        __syncthreads();

        if (ch == 0) {   // A frags + token norms (after sync: sA/sa ready)
            const u32 abase = sb + A_O + (u32)(warp * 16 + (lane & 15)) * (LDAB * 2)
                            + (u32)(lane >> 4) * 16;
#pragma unroll
            for (int ks = 0; ks < 6; ks++)
                ldmatrix_x4(af[ks][0], af[ks][1], af[ks][2], af[ks][3],
                            abase + (u32)ks * 32);
            float a_lo = sa[warp * 16 + gid];
            float a_hi = sa[warp * 16 + gid + 8];
            aal = pk2(a_lo, a_lo);
            aah = pk2(a_hi, a_hi);
        }

        // n-tiles: 8 codes each; B frag addresses from threads 0-15
        const u32 bbase0 = sb + B_O + (u32)(lane & 7) * (LDAB * 2)
                         + (u32)((lane & 15) >> 3) * 16;
#pragma unroll 1
        for (int nt = 0; nt < CN / 8; nt++) {
            float d0 = 0.f, d1 = 0.f, d2 = 0.f, d3 = 0.f;
            const u32 brow = bbase0 + (u32)nt * 8 * (LDAB * 2);
#pragma unroll
            for (int ks = 0; ks < 6; ks++) {
                u32 b0, b1;
                ldmatrix_x2(b0, b1, brow + (u32)ks * 32);    // NO trans
                mma16816(d0, d1, d2, d3,
                         af[ks][0], af[ks][1], af[ks][2], af[ks][3], b0, b1);
            }
            const int c0 = ch * CN + nt * 8 + tid4 * 2;
            const u64 bnp = *(const u64*)(sBn + c0);       // (bn[c0], bn[c0+1])
            u64 kl = ffma2(pk2(d0, d1), neg2, fadd2(aal, bnp));
            u64 kh = ffma2(pk2(d2, d3), neg2, fadd2(aah, bnp));
            float k0, k1;
            upk2(kl, k0, k1);
            m2[0] = fminf(m2[0], fmaxf(keyof(m1p[0]), k0));
            m1p[0] = umin64(m1p[0], pkkey(k0, c0));
            m2[0] = fminf(m2[0], fmaxf(keyof(m1p[0]), k1));
            m1p[0] = umin64(m1p[0], pkkey(k1, c0 + 1));
            upk2(kh, k0, k1);
            m2[1] = fminf(m2[1], fmaxf(keyof(m1p[1]), k0));
            m1p[1] = umin64(m1p[1], pkkey(k0, c0));
            m2[1] = fminf(m2[1], fmaxf(keyof(m1p[1]), k1));
            m1p[1] = umin64(m1p[1], pkkey(k1, c0 + 1));
        }
    }

    // ---- quad merge (tid4 lanes hold disjoint code subsets) ----
#pragma unroll
    for (int s = 0; s < 2; s++) {
#pragma unroll
        for (int off = 1; off <= 2; off <<= 1) {
            u64 om1 = __shfl_xor_sync(0xffffffffu, m1p[s], off);
            float om2 = __shfl_xor_sync(0xffffffffu, m2[s], off);
            m2[s] = fminf(fminf(m2[s], om2), fmaxf(keyof(m1p[s]), keyof(om1)));
            m1p[s] = umin64(m1p[s], om1);
        }
    }

    int fix[2] = {(int)(u32)m1p[0], (int)(u32)m1p[1]};

    // ---- exact rescue (owner lanes tid4==0; warp-cooperative rescan) ----
#pragma unroll
    for (int s = 0; s < 2; s++) {
        int amb = (tid4 == 0) && (m2[s] < __fadd_rn(keyof(m1p[s]), MARGIN));
        u32 bal = __ballot_sync(0xffffffffu, amb);
        while (bal) {
            const int src = __ffs(bal) - 1;
            bal &= bal - 1;
            const int row = warp * 16 + (src >> 2) + s * 8;
            const float* hr = sH + row * DIM;
            const float at = sa[row];
            float bd = INFP;
            int bix = 0;
#pragma unroll 1
            for (int w = 0; w < 32; w++) {
                const int code = lane + 32 * w;
                const float4* er = (const float4*)(E + (size_t)code * DIM);
                float acc = 0.0f;                    // reference chain
#pragma unroll
                for (int v = 0; v < 8; v++) {
                    float4 x = er[v];
                    acc = __fmaf_rn(x.x, hr[4*v+0], acc);
                    acc = __fmaf_rn(x.y, hr[4*v+1], acc);
                    acc = __fmaf_rn(x.z, hr[4*v+2], acc);
                    acc = __fmaf_rn(x.w, hr[4*v+3], acc);
                }
                float dd = __fmaf_rn(acc, -2.0f, __fadd_rn(at, sBn[code]));
                if (dd < bd) { bd = dd; bix = code; }
            }
#pragma unroll
            for (int o = 16; o; o >>= 1) {
                float od = __shfl_xor_sync(0xffffffffu, bd, o);
                int   oi = __shfl_xor_sync(0xffffffffu, bix, o);
                if (od < bd || (od == bd && oi < bix)) { bd = od; bix = oi; }
            }
            if (lane == src) fix[s] = bix;
        }
    }

    // ---- exact outputs (owner lanes; identical fp32 math to R5) ----
    if (tid4 == 0) {
#pragma unroll
        for (int s = 0; s < 2; s++) {
            const int row = warp * 16 + gid + s * 8;
            const int tok = blockIdx.x * TOKPC + row;
            const int bi  = fix[s];
            const float* h = sH + row * DIM;
            float q[DIM];
            const float4* qp = (const float4*)(E + (size_t)bi * DIM);
#pragma unroll
            for (int v = 0; v < 8; v++) {
                float4 x = qp[v];
                q[4*v+0] = x.x; q[4*v+1] = x.y; q[4*v+2] = x.z; q[4*v+3] = x.w;
            }
            float ss = sumsqdiff32(q, h);
            float L  = __fmul_rn(ss, 0.03125f);
            float l1 = __fmul_rn(L, 0.1f);
            float loss = __fadd_rn(l1, l1);

            float4* oq = (float4*)(out + (size_t)tok * DIM);
#pragma unroll
            for (int v = 0; v < 8; v++) {
                float4 r;
                r.x = __fadd_rn(h[4*v+0], __fsub_rn(q[4*v+0], h[4*v+0]));
                r.y = __fadd_rn(h[4*v+1], __fsub_rn(q[4*v+1], h[4*v+1]));
                r.z = __fadd_rn(h[4*v+2], __fsub_rn(q[4*v+2], h[4*v+2]));
                r.w = __fadd_rn(h[4*v+3], __fsub_rn(q[4*v+3], h[4*v+3]));
                oq[v] = r;
            }
            out[(size_t)NTOK * DIM + tok] = (float)bi;
            out[(size_t)NTOK * DIM + NTOK + tok] = loss;
        }
    }
}

extern "C" void kernel_launch(void* const* d_in, const int* in_sizes, int n_in,
                              void* d_out, int out_size) {
    (void)in_sizes; (void)n_in; (void)out_size;
    cudaFuncSetAttribute(vq_kernel, cudaFuncAttributeMaxDynamicSharedMemorySize,
                         SMEMSZ);
    vq_kernel<<<NBLK, TPB, SMEMSZ>>>((const float*)d_in[0],
                                     (const float*)d_in[1], (float*)d_out);
}